// round 15
// baseline (speedup 1.0000x reference)
#include <cuda_runtime.h>
#include <cstdint>

// ---------------- problem constants ----------------
#define B_SZ   32
#define CIN    128
#define H_IN   112
#define W_IN   112
#define COUT   256
#define OHW    55
#define STRIDE 2
#define M_TOT  (B_SZ * OHW * OHW)   // 96800
#define K_TOT  (CIN * 9)            // 1152
#define OPIX   (OHW * OHW)          // 3025
#define INHW   (H_IN * W_IN)        // 12544

// ---------------- GEMM tiling ----------------
#define BM 96
#define BN 256
#define BK 32
#define NT 384
#define KTILES (K_TOT / BK)         // 36
#define NSTAGE 4
#define PAIRED_TILES 24             // tiles 0..23: 16 cins x s{0,1}; 24..35: 32 cins x s=2

#define ASTRIDE 36
#define BSTRIDE 36
#define A_TILE_F (BM * ASTRIDE)     // 3456 floats
#define B_TILE_F (BN * BSTRIDE)     // 9216 floats
#define STAGE_F  (A_TILE_F + B_TILE_F)            // 12672 floats
#define SMEM_BYTES (NSTAGE * STAGE_F * 4)         // 202752

// A-operand truncation-bias compensation: mma.tf32 truncates raw fp32 A
// (mean relative shrink 2^-11); pre-scale B by (1 + 2^-11) to cancel.
#define BIAS_COMP 1.00048828125f

// scalar-tile permutation: k = step*8 + half*4 + qid -> pos = qid*8 + step*2 + half
__host__ __device__ __forceinline__ int kperm(int k) {
    return (k & 3) * 8 + ((k >> 3) << 1) + ((k >> 2) & 1);
}

// pre-converted (tf32, bias-compensated) weights in the custom (tile,pos) K-order
__device__ float g_wperm[COUT * K_TOT];

__device__ __forceinline__ uint32_t smem_u32(const void* p) {
    uint32_t a;
    asm("{ .reg .u64 t; cvta.to.shared.u64 t, %1; cvt.u32.u64 %0, t; }" : "=r"(a) : "l"(p));
    return a;
}
__device__ __forceinline__ uint32_t to_tf32(float f) {
    uint32_t u;
    asm("cvt.rna.tf32.f32 %0, %1;" : "=r"(u) : "f"(f));
    return u;
}

#define CP_ASYNC4(dst, src, sz) \
    asm volatile("cp.async.ca.shared.global [%0], [%1], 4, %2;" \
                 :: "r"(dst), "l"(src), "r"(sz) : "memory")
#define CP_ASYNC8(dst, src, sz) \
    asm volatile("cp.async.ca.shared.global [%0], [%1], 8, %2;" \
                 :: "r"(dst), "l"(src), "r"(sz) : "memory")
#define CP_ASYNC16(dst, src) \
    asm volatile("cp.async.cg.shared.global [%0], [%1], 16;" \
                 :: "r"(dst), "l"(src) : "memory")
#define CP_COMMIT()  asm volatile("cp.async.commit_group;" ::: "memory")
#define CP_WAIT2()   asm volatile("cp.async.wait_group 2;"  ::: "memory")
#define CP_WAIT1()   asm volatile("cp.async.wait_group 1;"  ::: "memory")
#define CP_WAIT0()   asm volatile("cp.async.wait_group 0;"  ::: "memory")

__device__ __forceinline__ void mma_tf32(float& c0, float& c1, float& c2, float& c3,
                                         uint32_t a0, uint32_t a1, uint32_t a2, uint32_t a3,
                                         uint32_t b0, uint32_t b1) {
    asm volatile("mma.sync.aligned.m16n8k8.row.col.f32.tf32.tf32.f32 "
                 "{%0,%1,%2,%3}, {%4,%5,%6,%7}, {%8,%9}, {%0,%1,%2,%3};"
                 : "+f"(c0), "+f"(c1), "+f"(c2), "+f"(c3)
                 : "r"(a0), "r"(a1), "r"(a2), "r"(a3), "r"(b0), "r"(b1));
}

// ---------------- weight pre-convert into (tile,pos) order ----------------
__global__ void prep_weights_kernel(const float* __restrict__ w)
{
    const int idx = blockIdx.x * blockDim.x + threadIdx.x;
    if (idx < COUT * K_TOT) {
        const int n   = idx / K_TOT;
        const int k   = idx - n * K_TOT;   // original: cin*9 + rs
        const int cin = k / 9;
        const int rs  = k - cin * 9;
        const int r   = rs / 3;
        const int s   = rs - r * 3;
        int t, pos;
        if (s < 2) {                        // paired tiles
            t = r * 8 + (cin >> 4);
            const int p = cin & 15;
            pos = (p >> 2) * 8 + (p & 3) * 2 + s;
        } else {                            // scalar tiles (s == 2)
            t = PAIRED_TILES + r * 4 + (cin >> 5);
            pos = kperm(cin & 31);
        }
        g_wperm[n * K_TOT + t * 32 + pos] =
            __uint_as_float(to_tf32(w[idx] * BIAS_COMP));
    }
}

// ---------------- main implicit-GEMM kernel ----------------
__global__ __launch_bounds__(NT, 1)
void conv_mma_tf32_kernel(const float* __restrict__ x,
                          float* __restrict__ out)
{
    extern __shared__ float sm[];
    const uint32_t sbase = smem_u32(sm);

    const int tid  = threadIdx.x;
    const int lane = tid & 31;
    const int wid  = tid >> 5;      // 0..11
    const int gid  = lane >> 2;     // 0..7
    const int qid  = lane & 3;      // 0..3
    const int warp_n = wid & 3;     // 0..3 -> n offset *64
    const int warp_m = wid >> 2;    // 0..2 -> m offset *32
    const int m0 = blockIdx.x * BM;

    // ---- A gather: 4 threads per m-row; thread owns quarter 'sub' of 32-k ----
    const int  mRow = tid >> 2;     // 0..95
    const int  sub  = tid & 3;      // 0..3
    const int  mG     = m0 + mRow;
    const bool mValid = (mG < M_TOT);
    const int  sz4    = mValid ? 4 : 0;
    const int  sz8    = mValid ? 8 : 0;
    const int  mc  = mValid ? mG : (M_TOT - 1);
    const int  bA  = mc / OPIX;
    const int  rA  = mc - bA * OPIX;
    const int  ohA = rA / OHW;
    const int  owA = rA - ohA * OHW;
    const float* xrow = x + (size_t)bA * CIN * INHW
                          + (size_t)(ohA * STRIDE) * W_IN + owA * STRIDE;

    auto load_a = [&](int buf, int kt) {
        const uint32_t dstrow = sbase + (uint32_t)(buf * STAGE_F + mRow * ASTRIDE) * 4u;
        if (kt < PAIRED_TILES) {
            // 16 cins x s{0,1}: 4 pairs per thread via cp.async.8
            const int r       = kt >> 3;
            const int cinbase = (kt & 7) * 16;
            const float* base = xrow + (size_t)(cinbase + sub * 4) * INHW + r * W_IN;   // s = 0
            const uint32_t d0 = dstrow + 4u * (uint32_t)(sub * 8);
            #pragma unroll
            for (int v = 0; v < 4; v++) {
                // pair p = sub*4 + v -> pos = sub*8 + v*2
                CP_ASYNC8(d0 + 4u * (uint32_t)(v * 2), base + (size_t)v * INHW, sz8);
            }
        } else {
            // 32 cins at s=2: 8 scalars per thread via cp.async.4
            const int j2      = kt - PAIRED_TILES;
            const int r       = j2 >> 2;
            const int cinbase = (j2 & 3) * 32;
            const float* base = xrow + (size_t)(cinbase + sub * 8) * INHW + r * W_IN + 2;
            const uint32_t d0 = dstrow + 4u * (uint32_t)(sub * 2);
            #pragma unroll
            for (int jj = 0; jj < 8; jj++) {
                // kl = sub*8 + jj -> pos = (jj&3)*8 + sub*2 + ((jj>>2)&1)
                const int posj = (jj & 3) * 8 + ((jj >> 2) & 1);
                CP_ASYNC4(d0 + 4u * (uint32_t)posj, base + (size_t)jj * INHW, sz4);
            }
        }
    };
    auto load_b = [&](int buf, int kt) {
        if (tid < 256) {
            #pragma unroll
            for (int p = 0; p < 8; p++) {
                const int idx = tid + 256 * p;
                const int row = idx >> 3;          // 0..255
                const int q   = idx & 7;
                const float* g = g_wperm + (size_t)row * K_TOT + kt * BK + q * 4;
                const uint32_t dst = sbase +
                    (uint32_t)(buf * STAGE_F + A_TILE_F + row * BSTRIDE + q * 4) * 4u;
                CP_ASYNC16(dst, g);
            }
        }
    };

    float acc[2][8][4];
    #pragma unroll
    for (int i = 0; i < 2; i++)
        #pragma unroll
        for (int j = 0; j < 8; j++)
            #pragma unroll
            for (int e = 0; e < 4; e++)
                acc[i][j][e] = 0.0f;

    // ---- prologue: prime 3 of 4 stages ----
    load_a(0, 0); load_b(0, 0); CP_COMMIT();
    load_a(1, 1); load_b(1, 1); CP_COMMIT();
    load_a(2, 2); load_b(2, 2); CP_COMMIT();

    #pragma unroll 1
    for (int kt = 0; kt < KTILES; kt++) {
        const int buf = kt & 3;
        if (kt <= KTILES - 3)      CP_WAIT2();
        else if (kt == KTILES - 2) CP_WAIT1();
        else                       CP_WAIT0();
        __syncthreads();

        // issue next loads immediately (stage (kt+3)&3 was last read at kt-1;
        // the sync above orders all its readers before these writes)
        if (kt + 3 < KTILES) {
            load_a((kt + 3) & 3, kt + 3);
            load_b((kt + 3) & 3, kt + 3);
            CP_COMMIT();
        }

        const float* A  = sm + buf * STAGE_F;
        const float* Bt = A + A_TILE_F;

        #pragma unroll
        for (int sp = 0; sp < 2; sp++) {          // step pairs
            uint4 av[2][2];
            #pragma unroll
            for (int mt = 0; mt < 2; mt++) {
                av[mt][0] = *(const uint4*)(A + (warp_m * 32 + mt * 16 + gid) * ASTRIDE + qid * 8 + sp * 4);
                av[mt][1] = *(const uint4*)(A + (warp_m * 32 + mt * 16 + gid + 8) * ASTRIDE + qid * 8 + sp * 4);
            }
            uint4 bv[8];
            #pragma unroll
            for (int nt = 0; nt < 8; nt++)
                bv[nt] = *(const uint4*)(Bt + (warp_n * 64 + nt * 8 + gid) * BSTRIDE + qid * 8 + sp * 4);

            // raw fp32 bits as tf32 A operands (HW truncation; bias folded into B)
            #pragma unroll
            for (int mt = 0; mt < 2; mt++) {
                #pragma unroll
                for (int nt = 0; nt < 8; nt++)
                    mma_tf32(acc[mt][nt][0], acc[mt][nt][1], acc[mt][nt][2], acc[mt][nt][3],
                             av[mt][0].x, av[mt][1].x, av[mt][0].y, av[mt][1].y,
                             bv[nt].x, bv[nt].y);
            }
            #pragma unroll
            for (int mt = 0; mt < 2; mt++) {
                #pragma unroll
                for (int nt = 0; nt < 8; nt++)
                    mma_tf32(acc[mt][nt][0], acc[mt][nt][1], acc[mt][nt][2], acc[mt][nt][3],
                             av[mt][0].z, av[mt][1].z, av[mt][0].w, av[mt][1].w,
                             bv[nt].z, bv[nt].w);
            }
        }
    }

    // ---- epilogue: direct register -> gmem scatter ----
    #pragma unroll
    for (int mt = 0; mt < 2; mt++) {
        const int mb = m0 + warp_m * 32 + mt * 16;
        #pragma unroll
        for (int half = 0; half < 2; half++) {
            const int m = mb + gid + half * 8;
            if (m < M_TOT) {
                const int b2  = m / OPIX;
                const int r2  = m - b2 * OPIX;
                const int oh2 = r2 / OHW;
                const int ow2 = r2 - oh2 * OHW;
                float* op = out + (size_t)b2 * COUT * OPIX + (size_t)oh2 * OHW + ow2;
                const int ncol0 = warp_n * 64 + qid * 2;
                #pragma unroll
                for (int nt = 0; nt < 8; nt++) {
                    const int n = ncol0 + nt * 8;
                    op[(size_t)n * OPIX]       = acc[mt][nt][half * 2 + 0];
                    op[(size_t)(n + 1) * OPIX] = acc[mt][nt][half * 2 + 1];
                }
            }
        }
    }
}

extern "C" void kernel_launch(void* const* d_in, const int* in_sizes, int n_in,
                              void* d_out, int out_size)
{
    const float* x = (const float*)d_in[0];
    const float* w = (const float*)d_in[1];
    float* out = (float*)d_out;

    cudaFuncSetAttribute(conv_mma_tf32_kernel,
                         cudaFuncAttributeMaxDynamicSharedMemorySize, SMEM_BYTES);

    prep_weights_kernel<<<(COUT * K_TOT + 255) / 256, 256>>>(w);

    const int grid = (M_TOT + BM - 1) / BM;   // 1009
    conv_mma_tf32_kernel<<<grid, NT, SMEM_BYTES>>>(x, out);
}

// round 17
// speedup vs baseline: 1.6998x; 1.6998x over previous
#include <cuda_runtime.h>
#include <cuda_fp16.h>
#include <cstdint>

// ---------------- problem constants ----------------
#define B_SZ   32
#define CIN    128
#define H_IN   112
#define W_IN   112
#define COUT   256
#define OHW    55
#define STRIDE 2
#define M_TOT  (B_SZ * OHW * OHW)   // 96800
#define K_TOT  (CIN * 9)            // 1152
#define OPIX   (OHW * OHW)          // 3025
#define INHW   (H_IN * W_IN)        // 12544

// ---------------- GEMM tiling ----------------
#define BM 128
#define BN 256
#define BK 32                       // 32 k = 16 fp16-pair words per row
#define NT 256
#define KTILES (K_TOT / BK)         // 36
#define NSTAGE 4
#define PAIRED_TILES 24             // tiles 0..23: 16 cins x s{0,1}; 24..35: 32 cins x s=2

// word layout per 32-k tile: 16 uint32 words (fp16 pairs), stride 16 (no pad),
// chunk c (4 words) holds logical words {c, c+4, c+8, c+12}; chunk position
// XOR-swizzled by ((row>>2)&3).
#define A_TILE_W (BM * 16)          // 2048 words
#define B_TILE_W (BN * 16)          // 4096 words
#define STAGE_W  (A_TILE_W + B_TILE_W)            // 6144 words
#define SMEM_BYTES (NSTAGE * STAGE_W * 4)         // 98304

// pre-packed fp16 weights: [COUT][KTILES][16 words]
__device__ uint32_t g_wword[COUT * KTILES * 16];

__device__ __forceinline__ uint32_t smem_u32(const void* p) {
    uint32_t a;
    asm("{ .reg .u64 t; cvta.to.shared.u64 t, %1; cvt.u32.u64 %0, t; }" : "=r"(a) : "l"(p));
    return a;
}

#define CP_ASYNC16(dst, src) \
    asm volatile("cp.async.cg.shared.global [%0], [%1], 16;" \
                 :: "r"(dst), "l"(src) : "memory")
#define CP_COMMIT()  asm volatile("cp.async.commit_group;" ::: "memory")
#define CP_WAIT2()   asm volatile("cp.async.wait_group 2;"  ::: "memory")
#define CP_WAIT1()   asm volatile("cp.async.wait_group 1;"  ::: "memory")
#define CP_WAIT0()   asm volatile("cp.async.wait_group 0;"  ::: "memory")

// pack (lo = even-k, hi = odd-k); PTX cvt packs first source into HIGH half
__device__ __forceinline__ uint32_t pack_h2(float lo, float hi) {
    uint32_t d;
    asm("cvt.rn.f16x2.f32 %0, %1, %2;" : "=r"(d) : "f"(hi), "f"(lo));
    return d;
}

__device__ __forceinline__ void mma_f16(float& c0, float& c1, float& c2, float& c3,
                                        uint32_t a0, uint32_t a1, uint32_t a2, uint32_t a3,
                                        uint32_t b0, uint32_t b1) {
    asm volatile("mma.sync.aligned.m16n8k16.row.col.f32.f16.f16.f32 "
                 "{%0,%1,%2,%3}, {%4,%5,%6,%7}, {%8,%9}, {%0,%1,%2,%3};"
                 : "+f"(c0), "+f"(c1), "+f"(c2), "+f"(c3)
                 : "r"(a0), "r"(a1), "r"(a2), "r"(a3), "r"(b0), "r"(b1));
}

// ---------------- weight pre-pack: fp16 pairs in (tile,pos) order ----------------
__global__ void prep_weights_kernel(const float* __restrict__ w)
{
    const int idx = blockIdx.x * blockDim.x + threadIdx.x;
    if (idx >= COUT * KTILES * 16) return;
    const int n   = idx / (KTILES * 16);
    const int rem = idx - n * (KTILES * 16);
    const int t   = rem >> 4;
    const int pos = rem & 15;
    const int wrd = (pos >> 2) + (pos & 3) * 4;   // logical word (inverse of pos map)

    float f[2];
    #pragma unroll
    for (int h2 = 0; h2 < 2; h2++) {
        int cin, rs;
        if (t < PAIRED_TILES) {                 // word = cin_local, halves = s
            const int r = t >> 3;
            cin = (t & 7) * 16 + wrd;
            rs  = r * 3 + h2;
        } else {                                // word holds cins (2w, 2w+1), s=2
            const int t2 = t - PAIRED_TILES;
            const int r  = t2 >> 2;
            cin = (t2 & 3) * 32 + wrd * 2 + h2;
            rs  = r * 3 + 2;
        }
        f[h2] = w[(size_t)n * K_TOT + cin * 9 + rs];
    }
    __half2 hv = __floats2half2_rn(f[0], f[1]);   // x = lo(even), y = hi(odd)
    g_wword[idx] = *reinterpret_cast<uint32_t*>(&hv);
}

// ---------------- main implicit-GEMM kernel ----------------
__global__ __launch_bounds__(NT, 1)
void conv_mma_f16_kernel(const float* __restrict__ x,
                         float* __restrict__ out)
{
    extern __shared__ uint32_t smw[];
    const uint32_t sbase = smem_u32(smw);

    const int tid  = threadIdx.x;
    const int lane = tid & 31;
    const int wid  = tid >> 5;
    const int gid  = lane >> 2;     // 0..7
    const int qid  = lane & 3;      // 0..3
    const int warp_m = wid & 1;     // 0..1 -> m offset *64
    const int warp_n = wid >> 1;    // 0..3 -> n offset *64
    const int m0 = blockIdx.x * BM;

    // ---- A gather: thread owns m-row = tid&127, k-half h = tid>>7 ----
    const int  mRow = tid & 127;
    const int  h    = tid >> 7;     // 0 or 1
    const int  mG     = m0 + mRow;
    const bool mValid = (mG < M_TOT);
    const int  mc  = mValid ? mG : (M_TOT - 1);
    const int  bA  = mc / OPIX;
    const int  rA  = mc - bA * OPIX;
    const int  ohA = rA / OHW;
    const int  owA = rA - ohA * OHW;
    const float* xrow = x + (size_t)bA * CIN * INHW
                          + (size_t)(ohA * STRIDE) * W_IN + owA * STRIDE;

    uint32_t aw[8];   // held packed words for one tile (software pipeline)

    auto ldg_a = [&](int kt) {
        if (kt < PAIRED_TILES) {
            const int r       = kt >> 3;
            const int cinbase = (kt & 7) * 16 + h * 8;
            const float* base = xrow + (size_t)cinbase * INHW + r * W_IN;
            #pragma unroll
            for (int j = 0; j < 8; j++) {
                float2 v = make_float2(0.f, 0.f);
                if (mValid) v = *(const float2*)(base + (size_t)j * INHW);
                aw[j] = pack_h2(v.x, v.y);          // lo = s0, hi = s1
            }
        } else {
            const int j2      = kt - PAIRED_TILES;
            const int r       = j2 >> 2;
            const int cinbase = (j2 & 3) * 32 + h * 16;
            const float* base = xrow + (size_t)cinbase * INHW + r * W_IN + 2;
            #pragma unroll
            for (int j = 0; j < 8; j++) {
                float f0 = 0.f, f1 = 0.f;
                if (mValid) {
                    f0 = base[(size_t)(2 * j) * INHW];
                    f1 = base[(size_t)(2 * j + 1) * INHW];
                }
                aw[j] = pack_h2(f0, f1);            // lo = even cin, hi = odd
            }
        }
    };
    auto sts_a = [&](int buf) {
        uint32_t* As = smw + buf * STAGE_W + mRow * 16 + 2 * h;
        const int sw = (mRow >> 2) & 3;
        #pragma unroll
        for (int c = 0; c < 4; c++) {
            // chunk c holds words {c, c+4} at in-chunk positions {2h, 2h+1}
            *(uint2*)(As + ((c ^ sw) << 2)) = make_uint2(aw[c], aw[c + 4]);
        }
    };
    auto load_b = [&](int buf, int kt) {
        #pragma unroll
        for (int p = 0; p < 4; p++) {
            const int idx = tid + NT * p;      // 0..1023
            const int row = idx >> 2;          // 0..255
            const int c   = idx & 3;
            const uint32_t* g = g_wword + (size_t)row * (KTILES * 16) + kt * 16 + c * 4;
            const int sw = (row >> 2) & 3;
            const uint32_t dst = sbase +
                (uint32_t)(buf * STAGE_W + A_TILE_W + row * 16 + ((c ^ sw) << 2)) * 4u;
            CP_ASYNC16(dst, g);
        }
    };

    float acc[4][8][4];
    #pragma unroll
    for (int i = 0; i < 4; i++)
        #pragma unroll
        for (int j = 0; j < 8; j++)
            #pragma unroll
            for (int e = 0; e < 4; e++)
                acc[i][j][e] = 0.0f;

    // ---- prologue ----
    ldg_a(0); sts_a(0);
    ldg_a(1); sts_a(1);
    ldg_a(2); sts_a(2);
    load_b(0, 0); CP_COMMIT();
    load_b(1, 1); CP_COMMIT();
    load_b(2, 2); CP_COMMIT();
    ldg_a(3);      // held for iter 0

    #pragma unroll 1
    for (int kt = 0; kt < KTILES; kt++) {
        const int buf = kt & 3;
        if (kt <= KTILES - 3)      CP_WAIT2();
        else if (kt == KTILES - 2) CP_WAIT1();
        else                       CP_WAIT0();
        __syncthreads();

        if (kt + 3 < KTILES) {
            sts_a((kt + 3) & 3);                     // from held regs
            load_b((kt + 3) & 3, kt + 3); CP_COMMIT();
            if (kt + 4 < KTILES) ldg_a(kt + 4);      // refill held regs
        }

        const uint32_t* A  = smw + buf * STAGE_W;
        const uint32_t* Bt = A + A_TILE_W;

        // fragment loads: one LDS.128 per (row): covers both k16 blocks
        uint4 av[4][2];
        #pragma unroll
        for (int mt = 0; mt < 4; mt++) {
            const int r0 = warp_m * 64 + mt * 16 + gid;
            const int r1 = r0 + 8;
            av[mt][0] = *(const uint4*)(A + r0 * 16 + ((qid ^ ((r0 >> 2) & 3)) << 2));
            av[mt][1] = *(const uint4*)(A + r1 * 16 + ((qid ^ ((r1 >> 2) & 3)) << 2));
        }
        uint4 bv[8];
        #pragma unroll
        for (int nt = 0; nt < 8; nt++) {
            const int rn = warp_n * 64 + nt * 8 + gid;
            bv[nt] = *(const uint4*)(Bt + rn * 16 + ((qid ^ ((rn >> 2) & 3)) << 2));
        }

        // k16 block 0 (words .x = k(2q,2q+1), .y = k(2q+8,2q+9))
        #pragma unroll
        for (int mt = 0; mt < 4; mt++)
            #pragma unroll
            for (int nt = 0; nt < 8; nt++)
                mma_f16(acc[mt][nt][0], acc[mt][nt][1], acc[mt][nt][2], acc[mt][nt][3],
                        av[mt][0].x, av[mt][1].x, av[mt][0].y, av[mt][1].y,
                        bv[nt].x, bv[nt].y);
        // k16 block 1 (words .z, .w)
        #pragma unroll
        for (int mt = 0; mt < 4; mt++)
            #pragma unroll
            for (int nt = 0; nt < 8; nt++)
                mma_f16(acc[mt][nt][0], acc[mt][nt][1], acc[mt][nt][2], acc[mt][nt][3],
                        av[mt][0].z, av[mt][1].z, av[mt][0].w, av[mt][1].w,
                        bv[nt].z, bv[nt].w);
    }

    // ---- epilogue: direct register -> gmem scatter ----
    #pragma unroll
    for (int mt = 0; mt < 4; mt++) {
        const int mb = m0 + warp_m * 64 + mt * 16;
        #pragma unroll
        for (int half = 0; half < 2; half++) {
            const int m = mb + gid + half * 8;
            if (m < M_TOT) {
                const int b2  = m / OPIX;
                const int r2  = m - b2 * OPIX;
                const int oh2 = r2 / OHW;
                const int ow2 = r2 - oh2 * OHW;
                float* op = out + (size_t)b2 * COUT * OPIX + (size_t)oh2 * OHW + ow2;
                const int ncol0 = warp_n * 64 + qid * 2;
                #pragma unroll
                for (int nt = 0; nt < 8; nt++) {
                    const int n = ncol0 + nt * 8;
                    op[(size_t)n * OPIX]       = acc[mt][nt][half * 2 + 0];
                    op[(size_t)(n + 1) * OPIX] = acc[mt][nt][half * 2 + 1];
                }
            }
        }
    }
}

extern "C" void kernel_launch(void* const* d_in, const int* in_sizes, int n_in,
                              void* d_out, int out_size)
{
    const float* x = (const float*)d_in[0];
    const float* w = (const float*)d_in[1];
    float* out = (float*)d_out;

    cudaFuncSetAttribute(conv_mma_f16_kernel,
                         cudaFuncAttributeMaxDynamicSharedMemorySize, SMEM_BYTES);

    prep_weights_kernel<<<(COUT * KTILES * 16 + 255) / 256, 256>>>(w);

    const int grid = (M_TOT + BM - 1) / BM;   // 757
    conv_mma_f16_kernel<<<grid, NT, SMEM_BYTES>>>(x, out);
}